// round 11
// baseline (speedup 1.0000x reference)
#include <cuda_runtime.h>
#include <math.h>

// Problem constants
#define HW   4096      // 64*64
#define BB   8         // batch
#define NS   256       // sampled points (16*16)

typedef unsigned long long u64;

// ---- f32x2 packed math (Blackwell; FFMA2 only reachable via PTX) -----------
__device__ __forceinline__ u64 f2fma(u64 a, u64 b, u64 c) {
    u64 d; asm("fma.rn.f32x2 %0,%1,%2,%3;" : "=l"(d) : "l"(a), "l"(b), "l"(c)); return d;
}
__device__ __forceinline__ u64 f2add(u64 a, u64 b) {
    u64 d; asm("add.rn.f32x2 %0,%1,%2;" : "=l"(d) : "l"(a), "l"(b)); return d;
}
__device__ __forceinline__ u64 fpack(float lo, float hi) {
    u64 d; asm("mov.b64 %0,{%1,%2};" : "=l"(d) : "f"(lo), "f"(hi)); return d;
}
__device__ __forceinline__ float2 funpack(u64 v) {
    float2 r; asm("mov.b64 {%0,%1},%2;" : "=f"(r.x), "=f"(r.y) : "l"(v)); return r;
}

// ---------------- scratch (device globals; no allocation allowed) -----------
__device__ float  g_q[3 * BB * 64 * HW];      // q projection  [bi][b][c][m]
__device__ float  g_attn[3 * BB * 64 * HW];   // attention out [bi][b][c][m]
__device__ float  g_pos[3 * BB * NS * 2];     // positions (y,x) in [-1,1]
__device__ float  g_k[3 * BB * 64 * NS];
__device__ float  g_v[3 * BB * 64 * NS];
__device__ float2 g_rpe2[3 * 4 * 127 * 127];  // (rpe[y][x], rpe[y][x+1]) pairs

// ---------------- K1: q = conv1x1(x[:, :64]) -> g_q ; + rpe prep blocks -----
__global__ void k_qproj(const float* __restrict__ x1, const float* __restrict__ x2,
                        const float* __restrict__ pq_w, const float* __restrict__ pq_b,
                        const float* __restrict__ rpe) {
    int blk = blockIdx.x;
    int t = threadIdx.x;
    if (blk >= 384) {                      // rpe pair-prep: blocks 384..1140
        int i = (blk - 384) * 256 + t;
        if (i < 3 * 4 * 127 * 127) {
            int x = i % 127, rest = i / 127;
            float a = rpe[rest * 127 + x];
            float bv = (x < 126) ? rpe[rest * 127 + x + 1] : a;
            g_rpe2[i] = make_float2(a, bv);
        }
        return;
    }
    __shared__ float ws[4096];
    int bi = blk >> 7, ib = blk & 127;
    const float* w = pq_w + bi * 4096;
    const float* bias = pq_b + bi * 64;
    const float* x = (bi == 0) ? x1 : x2;   // QI = {1,2,2}
    for (int i = t; i < 4096; i += 256) ws[(i & 63) * 64 + (i >> 6)] = w[i];
    __syncthreads();
    int p = ib * 256 + t, b = p >> 12, m = p & 4095;
    const float* xp = x + (size_t)b * 128 * HW + m;
    u64 acc[32];
#pragma unroll
    for (int j = 0; j < 32; j++) acc[j] = fpack(bias[2 * j], bias[2 * j + 1]);
    for (int c = 0; c < 64; c++) {
        float xv = xp[(size_t)c * HW];
        u64 pp = fpack(xv, xv);
        const ulonglong2* wr = (const ulonglong2*)(ws + c * 64);
#pragma unroll
        for (int j2 = 0; j2 < 16; j2++) {
            ulonglong2 wv = wr[j2];
            acc[2 * j2]     = f2fma(pp, wv.x, acc[2 * j2]);
            acc[2 * j2 + 1] = f2fma(pp, wv.y, acc[2 * j2 + 1]);
        }
    }
    float* op = g_q + (size_t)bi * BB * 64 * HW + (size_t)b * 64 * HW + m;
#pragma unroll
    for (int j = 0; j < 32; j++) {
        float2 v = funpack(acc[j]);
        op[(size_t)(2 * j) * HW] = v.x;
        op[(size_t)(2 * j + 1) * HW] = v.y;
    }
}

// ---------------- K2: offset head + kv sample/project (fused, batched) ------
__global__ void k_offkv(const float* __restrict__ x0, const float* __restrict__ x1,
                        const float* __restrict__ dw_w, const float* __restrict__ dw_b,
                        const float* __restrict__ ln_g, const float* __restrict__ ln_b,
                        const float* __restrict__ pw_w,
                        const float* __restrict__ pk_w, const float* __restrict__ pk_b,
                        const float* __restrict__ pv_w, const float* __restrict__ pv_b) {
    __shared__ float off_s[1024];
    __shared__ float stats[32];
    __shared__ float pos_s[16][2];
    __shared__ float wk_s[4096];
    __shared__ float wv_s[4096];
    __shared__ float xs_s[16][64];
    int blk = blockIdx.x, bi = blk >> 7, ib = blk & 127;
    int b = ib >> 4, hk = ib & 15;
    int t = threadIdx.x, wk = t & 15, cq = t >> 4;
    const float* pkw = pk_w + bi * 4096;
    const float* pvw = pv_w + bi * 4096;
    for (int i = t; i < 4096; i += 256) {
        int o = i >> 6, c = i & 63;
        wk_s[c * 64 + o] = pkw[i];
        wv_s[c * 64 + o] = pvw[i];
    }
    const float* dww = dw_w + bi * 1024;
    const float* dwb = dw_b + bi * 64;
    const float* lng = ln_g + bi * 64;
    const float* lnb = ln_b + bi * 64;
    const float* pww = pw_w + bi * 128;
    const float* gq = g_q + (size_t)bi * BB * 64 * HW;
#pragma unroll
    for (int j = 0; j < 4; j++) {
        int c = cq * 4 + j;
        const float* qp = gq + ((size_t)b * 64 + c) * HW + hk * 4 * 64 + wk * 4;
        const float* wp = dww + c * 16;
        float s = dwb[c];
#pragma unroll
        for (int ky = 0; ky < 4; ky++)
#pragma unroll
            for (int kx = 0; kx < 4; kx++)
                s += qp[ky * 64 + kx] * wp[ky * 4 + kx];
        off_s[c * 16 + wk] = s;
    }
    __syncthreads();
    if (t < 16) {
        float s = 0.f, s2 = 0.f;
        for (int c = 0; c < 64; c++) { float v = off_s[c * 16 + t]; s += v; s2 += v * v; }
        float mu = s * (1.f / 64.f);
        float var = s2 * (1.f / 64.f) - mu * mu;
        stats[t * 2] = mu;
        stats[t * 2 + 1] = rsqrtf(var + 1e-5f);
    }
    __syncthreads();
    {
        float mu = stats[wk * 2], inv = stats[wk * 2 + 1];
#pragma unroll
        for (int j = 0; j < 4; j++) {
            int c = cq * 4 + j;
            float v = (off_s[c * 16 + wk] - mu) * inv * lng[c] + lnb[c];
            v = 0.5f * v * (1.f + erff(v * 0.70710678118654752f));
            off_s[c * 16 + wk] = v;
        }
    }
    __syncthreads();
    if (t < 32) {
        int wk2 = t & 15, o = t >> 4;
        const float* pw = pww + o * 64;
        float s = 0.f;
        for (int c = 0; c < 64; c++) s += pw[c] * off_s[c * 16 + wk2];
        float refc = (o == 0) ? ((hk + 0.5f) * (1.f / 15.f) * 2.f - 1.f)
                              : ((wk2 + 0.5f) * (1.f / 15.f) * 2.f - 1.f);
        float p = fminf(fmaxf(s + refc, -1.f), 1.f);
        pos_s[wk2][o] = p;
        g_pos[(size_t)bi * BB * NS * 2 + ((size_t)b * NS + hk * 16 + wk2) * 2 + o] = p;
    }
    __syncthreads();
    const float* xkv = (bi < 2) ? x0 : x1;   // KVJ = {0,0,1}
    const float* pkb = pk_b + bi * 64;
    const float* pvb = pv_b + bi * 64;
    int wi = t >> 5, lane = t & 31;
#pragma unroll
    for (int kk = 0; kk < 2; kk++) {
        int nl = wi * 2 + kk;
        float py = pos_s[nl][0], px = pos_s[nl][1];
        float xi = (px + 1.f) * 31.5f;
        float yi = (py + 1.f) * 31.5f;
        float xf = floorf(xi), yf = floorf(yi);
        float wx = xi - xf, wy = yi - yf;
        int x0i = (int)xf, y0i = (int)yf;
        int x1i = min(x0i + 1, 63), y1i = min(y0i + 1, 63);
        float w00 = (1.f - wy) * (1.f - wx), w01 = (1.f - wy) * wx;
        float w10 = wy * (1.f - wx),         w11 = wy * wx;
#pragma unroll
        for (int ci = 0; ci < 2; ci++) {
            int c = lane + ci * 32;
            const float* p = xkv + ((size_t)b * 128 + c) * HW;
            float s = p[y0i * 64 + x0i] * w00 + p[y0i * 64 + x1i] * w01
                    + p[y1i * 64 + x0i] * w10 + p[y1i * 64 + x1i] * w11;
            xs_s[nl][c] = s;
        }
    }
    __syncwarp();
#pragma unroll
    for (int kk = 0; kk < 2; kk++) {
        int nl = wi * 2 + kk;
        int n = hk * 16 + nl;
        float ak0 = pkb[lane], ak1 = pkb[lane + 32];
        float av0 = pvb[lane], av1 = pvb[lane + 32];
        for (int c = 0; c < 64; c++) {
            float xv = xs_s[nl][c];
            ak0 += wk_s[c * 64 + lane]      * xv;
            ak1 += wk_s[c * 64 + lane + 32] * xv;
            av0 += wv_s[c * 64 + lane]      * xv;
            av1 += wv_s[c * 64 + lane + 32] * xv;
        }
        size_t base = (size_t)bi * BB * 64 * NS;
        g_k[base + ((size_t)b * 64 + lane)      * NS + n] = ak0;
        g_k[base + ((size_t)b * 64 + lane + 32) * NS + n] = ak1;
        g_v[base + ((size_t)b * 64 + lane)      * NS + n] = av0;
        g_v[base + ((size_t)b * 64 + lane + 32) * NS + n] = av1;
    }
}

// ---------------- K3: fused attention, 4 queries/thread, 3 blocks/SM --------
// block = (bi, b, tile of 512 queries (8 rows), head); 128 threads.
// thread t: col c = t&63, row-group rg = t>>6 -> 4 queries at rows my0..my0+3.
// Single-buffered rpe loads (issued at top of each 2-key group); extra resident
// warps (3 blocks/SM) hide the L2 latency instead of a register double-buffer.
__global__ void __launch_bounds__(128, 3) k_attn() {
    __shared__ float ks[NS * 16];
    __shared__ float vs[NS * 16];
    __shared__ int boff[NS];
    __shared__ ulonglong2 bwp[NS];
    int blk = blockIdx.x;
    int bi = blk >> 8, inner = blk & 255;
    int h = inner & 3, tile = (inner >> 2) & 7, b = inner >> 5;
    int t = threadIdx.x;
    const float* gk = g_k + (size_t)bi * BB * 64 * NS;
    const float* gv = g_v + (size_t)bi * BB * 64 * NS;
    const float* gp = g_pos + (size_t)bi * BB * NS * 2;
    for (int i = t; i < 4096; i += 128) {
        int c = i >> 8, n = i & 255;
        ks[n * 16 + c] = gk[((size_t)b * 64 + h * 16 + c) * NS + n];
        vs[n * 16 + c] = gv[((size_t)b * 64 + h * 16 + c) * NS + n];
    }
    for (int n = t; n < NS; n += 128) {   // per-key bias precompute
        float py = gp[((size_t)b * NS + n) * 2];
        float px = gp[((size_t)b * NS + n) * 2 + 1];
        float cx = 31.5f * (1.f - px);
        float cy = 31.5f * (1.f - py);
        int ix = (int)floorf(cx), iy = (int)floorf(cy);
        float wx = cx - (float)ix, wy = cy - (float)iy;
        if (ix >= 63) { ix = 62; wx = 1.f; }
        if (iy >= 63) { iy = 62; wy = 1.f; }
        boff[n] = iy * 127 + ix;
        bwp[n] = make_ulonglong2(fpack((1.f - wy) * (1.f - wx), (1.f - wy) * wx),
                                 fpack(wy * (1.f - wx), wy * wx));
    }
    __syncthreads();
    int c63 = t & 63, rg = t >> 6;
    int my0 = tile * 8 + rg * 4;          // rows my0..my0+3
    int m0 = my0 * 64 + c63;
    const float* gq = g_q + (size_t)bi * BB * 64 * HW + ((size_t)b * 64 + h * 16) * HW + m0;
    u64 q[4][8];
#pragma unroll
    for (int j = 0; j < 8; j++)
#pragma unroll
        for (int i = 0; i < 4; i++)
            q[i][j] = fpack(gq[(size_t)(2 * j) * HW + i * 64]     * 0.25f,
                            gq[(size_t)(2 * j + 1) * HW + i * 64] * 0.25f);
    const float2* rp2 = g_rpe2 + ((size_t)(bi * 4 + h) * 127 * 127) + my0 * 127 + c63;
    float ss0 = 0.f, ss1 = 0.f, ss2 = 0.f, ss3 = 0.f;
    u64 Z = 0ULL;
    u64 acc[4][8];
#pragma unroll
    for (int i = 0; i < 4; i++)
#pragma unroll
        for (int j = 0; j < 8; j++) acc[i][j] = Z;
#pragma unroll 2
    for (int g = 0; g < 128; g++) {
        // single-buffer rpe loads for this 2-key group, issued up front
        u64 R[2][5];
#pragma unroll
        for (int j = 0; j < 2; j++) {
            const u64* ap = (const u64*)(rp2 + boff[2 * g + j]);
#pragma unroll
            for (int r = 0; r < 5; r++) R[j][r] = ap[r * 127];
        }
#pragma unroll
        for (int j = 0; j < 2; j++) {
            int n = 2 * g + j;
            const ulonglong2* kp = (const ulonglong2*)(ks + n * 16);
            ulonglong2 kA = kp[0], kB = kp[1], kC = kp[2], kD = kp[3];
            ulonglong2 w = bwp[n];
            const ulonglong2* vp = (const ulonglong2*)(vs + n * 16);
            ulonglong2 vA = vp[0], vB = vp[1], vC = vp[2], vD = vp[3];
            float p[4];
#pragma unroll
            for (int i = 0; i < 4; i++) {
                // QK chain first; bias (which waits on the LDGs) joins at the end
                u64 u = f2fma(q[i][0], kA.x, f2fma(q[i][2], kB.x,
                        f2fma(q[i][4], kC.x, f2fma(q[i][6], kD.x, Z))));
                u64 v = f2fma(q[i][1], kA.y, f2fma(q[i][3], kB.y,
                        f2fma(q[i][5], kC.y, f2fma(q[i][7], kD.y, Z))));
                u64 bb = f2fma(w.x, R[j][i], f2fma(w.y, R[j][i + 1], Z));
                float2 s = funpack(f2add(f2add(u, v), bb));
                p[i] = __expf(s.x + s.y);   // |logit| is O(5): no-max softmax safe
            }
            ss0 += p[0]; ss1 += p[1]; ss2 += p[2]; ss3 += p[3];
#pragma unroll
            for (int i = 0; i < 4; i++) {
                u64 pp = fpack(p[i], p[i]);
                acc[i][0] = f2fma(pp, vA.x, acc[i][0]);
                acc[i][1] = f2fma(pp, vA.y, acc[i][1]);
                acc[i][2] = f2fma(pp, vB.x, acc[i][2]);
                acc[i][3] = f2fma(pp, vB.y, acc[i][3]);
                acc[i][4] = f2fma(pp, vC.x, acc[i][4]);
                acc[i][5] = f2fma(pp, vC.y, acc[i][5]);
                acc[i][6] = f2fma(pp, vD.x, acc[i][6]);
                acc[i][7] = f2fma(pp, vD.y, acc[i][7]);
            }
        }
    }
    float inv[4] = { 1.f / ss0, 1.f / ss1, 1.f / ss2, 1.f / ss3 };
    float* oa = g_attn + (size_t)bi * BB * 64 * HW + ((size_t)b * 64 + h * 16) * HW + m0;
#pragma unroll
    for (int i = 0; i < 4; i++)
#pragma unroll
        for (int j = 0; j < 8; j++) {
            float2 v = funpack(acc[i][j]);
            oa[(size_t)(2 * j) * HW + i * 64]     = v.x * inv[i];
            oa[(size_t)(2 * j + 1) * HW + i * 64] = v.y * inv[i];
        }
}

// ---------------- K4: out proj + base copy ----------------------------------
// blocks 0..255: out = x[64:128] + proj(attn); blocks 256..1023: base copy.
__global__ void k_oproj(const float* __restrict__ po_w, const float* __restrict__ po_b,
                        const float4* __restrict__ x0f, const float* __restrict__ x1,
                        const float* __restrict__ x2, float* __restrict__ out) {
    int blk = blockIdx.x;
    int t = threadIdx.x;
    if (blk >= 256) {                     // base copy: lvl0 full, lvl1/2 first-64ch
        const int FULL = 1048576;         // float4 per level
        const int HALF = 524288;
        const float4* x1f = (const float4*)x1;
        const float4* x2f = (const float4*)x2;
        float4* outf = (float4*)out;
        for (int i = (blk - 256) * 256 + t; i < FULL + 2 * HALF; i += 768 * 256) {
            if (i < FULL) { outf[i] = x0f[i]; continue; }
            int j = i - FULL;
            int l = (j < HALF) ? 1 : 2;
            int jj = j - (l - 1) * HALF;
            int b = jj >> 16;
            int rem = jj & 65535;
            const float4* src = (l == 1) ? x1f : x2f;
            outf[(size_t)l * FULL + (size_t)b * 131072 + rem] = src[(size_t)b * 131072 + rem];
        }
        return;
    }
    __shared__ float ws[2][4096];
    int lvl2 = blk >> 7, ib = blk & 127;
    if (!lvl2) {
        for (int i = t; i < 4096; i += 256) ws[0][(i & 63) * 64 + (i >> 6)] = po_w[i];
    } else {
        for (int i = t; i < 4096; i += 256) {
            ws[0][(i & 63) * 64 + (i >> 6)] = po_w[4096 + i];
            ws[1][(i & 63) * 64 + (i >> 6)] = po_w[8192 + i];
        }
    }
    __syncthreads();
    int p = ib * 256 + t, b = p >> 12, m = p & 4095;
    u64 acc[32];
    if (!lvl2) {
#pragma unroll
        for (int j = 0; j < 32; j++) acc[j] = fpack(po_b[2 * j], po_b[2 * j + 1]);
        const float* xp = g_attn + (size_t)b * 64 * HW + m;
        for (int c = 0; c < 64; c++) {
            float xv = xp[(size_t)c * HW];
            u64 pp = fpack(xv, xv);
            const ulonglong2* wr = (const ulonglong2*)(ws[0] + c * 64);
#pragma unroll
            for (int j2 = 0; j2 < 16; j2++) {
                ulonglong2 wv = wr[j2];
                acc[2 * j2]     = f2fma(pp, wv.x, acc[2 * j2]);
                acc[2 * j2 + 1] = f2fma(pp, wv.y, acc[2 * j2 + 1]);
            }
        }
        const float* xs = x1 + ((size_t)b * 128 + 64) * HW + m;
        float* op = out + (size_t)1 * BB * 128 * HW + ((size_t)b * 128 + 64) * HW + m;
#pragma unroll
        for (int j = 0; j < 32; j++) {
            float2 v = funpack(acc[j]);
            op[(size_t)(2 * j) * HW]     = xs[(size_t)(2 * j) * HW] + v.x;
            op[(size_t)(2 * j + 1) * HW] = xs[(size_t)(2 * j + 1) * HW] + v.y;
        }
    } else {
#pragma unroll
        for (int j = 0; j < 32; j++)
            acc[j] = fpack(po_b[64 + 2 * j] + po_b[128 + 2 * j],
                           po_b[64 + 2 * j + 1] + po_b[128 + 2 * j + 1]);
        const float* xp1 = g_attn + (size_t)1 * BB * 64 * HW + (size_t)b * 64 * HW + m;
        const float* xp2 = g_attn + (size_t)2 * BB * 64 * HW + (size_t)b * 64 * HW + m;
        for (int c = 0; c < 64; c++) {
            float x1v = xp1[(size_t)c * HW];
            float x2v = xp2[(size_t)c * HW];
            u64 p1 = fpack(x1v, x1v), p2 = fpack(x2v, x2v);
            const ulonglong2* w1 = (const ulonglong2*)(ws[0] + c * 64);
            const ulonglong2* w2 = (const ulonglong2*)(ws[1] + c * 64);
#pragma unroll
            for (int j2 = 0; j2 < 16; j2++) {
                ulonglong2 wv1 = w1[j2], wv2 = w2[j2];
                acc[2 * j2]     = f2fma(p1, wv1.x, f2fma(p2, wv2.x, acc[2 * j2]));
                acc[2 * j2 + 1] = f2fma(p1, wv1.y, f2fma(p2, wv2.y, acc[2 * j2 + 1]));
            }
        }
        const float* xs = x2 + ((size_t)b * 128 + 64) * HW + m;
        float* op = out + (size_t)2 * BB * 128 * HW + ((size_t)b * 128 + 64) * HW + m;
#pragma unroll
        for (int j = 0; j < 32; j++) {
            float2 v = funpack(acc[j]);
            op[(size_t)(2 * j) * HW]     = xs[(size_t)(2 * j) * HW] + v.x;
            op[(size_t)(2 * j + 1) * HW] = xs[(size_t)(2 * j + 1) * HW] + v.y;
        }
    }
}

// ---------------- host ------------------------------------------------------
extern "C" void kernel_launch(void* const* d_in, const int* in_sizes, int n_in,
                              void* d_out, int out_size) {
    const float* x0   = (const float*)d_in[0];
    const float* x1   = (const float*)d_in[1];
    const float* x2   = (const float*)d_in[2];
    const float* pq_w = (const float*)d_in[3];
    const float* pq_b = (const float*)d_in[4];
    const float* dw_w = (const float*)d_in[5];
    const float* dw_b = (const float*)d_in[6];
    const float* ln_g = (const float*)d_in[7];
    const float* ln_b = (const float*)d_in[8];
    const float* pw_w = (const float*)d_in[9];
    const float* pk_w = (const float*)d_in[10];
    const float* pk_b = (const float*)d_in[11];
    const float* pv_w = (const float*)d_in[12];
    const float* pv_b = (const float*)d_in[13];
    const float* po_w = (const float*)d_in[14];
    const float* po_b = (const float*)d_in[15];
    const float* rpe  = (const float*)d_in[16];
    float* out = (float*)d_out;

    k_qproj<<<1141, 256>>>(x1, x2, pq_w, pq_b, rpe);     // 384 proj + 757 rpe-prep
    k_offkv<<<384, 256>>>(x0, x1, dw_w, dw_b, ln_g, ln_b, pw_w,
                          pk_w, pk_b, pv_w, pv_b);
    k_attn<<<768, 128>>>();
    k_oproj<<<1024, 256>>>(po_w, po_b, (const float4*)x0, x1, x2, out);  // 256 proj + 768 copy
}

// round 12
// speedup vs baseline: 1.1633x; 1.1633x over previous
#include <cuda_runtime.h>
#include <math.h>

// Problem constants
#define HW   4096      // 64*64
#define BB   8         // batch
#define NS   256       // sampled points (16*16)

typedef unsigned long long u64;

// ---- f32x2 packed math (Blackwell; FFMA2 only reachable via PTX) -----------
__device__ __forceinline__ u64 f2fma(u64 a, u64 b, u64 c) {
    u64 d; asm("fma.rn.f32x2 %0,%1,%2,%3;" : "=l"(d) : "l"(a), "l"(b), "l"(c)); return d;
}
__device__ __forceinline__ u64 f2add(u64 a, u64 b) {
    u64 d; asm("add.rn.f32x2 %0,%1,%2;" : "=l"(d) : "l"(a), "l"(b)); return d;
}
__device__ __forceinline__ u64 fpack(float lo, float hi) {
    u64 d; asm("mov.b64 %0,{%1,%2};" : "=l"(d) : "f"(lo), "f"(hi)); return d;
}
__device__ __forceinline__ float2 funpack(u64 v) {
    float2 r; asm("mov.b64 {%0,%1},%2;" : "=f"(r.x), "=f"(r.y) : "l"(v)); return r;
}

#define LOG2E 1.4426950408889634f

// ---------------- scratch (device globals; no allocation allowed) -----------
__device__ float  g_q[3 * BB * 64 * HW];      // q projection  [bi][b][c][m]
__device__ float  g_attn[3 * BB * 64 * HW];   // attention out [bi][b][c][m]
__device__ float  g_pos[3 * BB * NS * 2];     // positions (y,x) in [-1,1]
__device__ float  g_k[3 * BB * 64 * NS];
__device__ float  g_v[3 * BB * 64 * NS];
__device__ float2 g_rpe2[3 * 4 * 127 * 127];  // (rpe[y][x], rpe[y][x+1]) pairs

// ---------------- K1: q = conv1x1(x[:, :64]) -> g_q ; + rpe prep blocks -----
__global__ void k_qproj(const float* __restrict__ x1, const float* __restrict__ x2,
                        const float* __restrict__ pq_w, const float* __restrict__ pq_b,
                        const float* __restrict__ rpe) {
    int blk = blockIdx.x;
    int t = threadIdx.x;
    if (blk >= 384) {                      // rpe pair-prep: blocks 384..1140
        int i = (blk - 384) * 256 + t;
        if (i < 3 * 4 * 127 * 127) {
            int x = i % 127, rest = i / 127;
            float a = rpe[rest * 127 + x];
            float bv = (x < 126) ? rpe[rest * 127 + x + 1] : a;
            g_rpe2[i] = make_float2(a, bv);
        }
        return;
    }
    __shared__ float ws[4096];
    int bi = blk >> 7, ib = blk & 127;
    const float* w = pq_w + bi * 4096;
    const float* bias = pq_b + bi * 64;
    const float* x = (bi == 0) ? x1 : x2;   // QI = {1,2,2}
    for (int i = t; i < 4096; i += 256) ws[(i & 63) * 64 + (i >> 6)] = w[i];
    __syncthreads();
    int p = ib * 256 + t, b = p >> 12, m = p & 4095;
    const float* xp = x + (size_t)b * 128 * HW + m;
    u64 acc[32];
#pragma unroll
    for (int j = 0; j < 32; j++) acc[j] = fpack(bias[2 * j], bias[2 * j + 1]);
    for (int c = 0; c < 64; c++) {
        float xv = xp[(size_t)c * HW];
        u64 pp = fpack(xv, xv);
        const ulonglong2* wr = (const ulonglong2*)(ws + c * 64);
#pragma unroll
        for (int j2 = 0; j2 < 16; j2++) {
            ulonglong2 wv = wr[j2];
            acc[2 * j2]     = f2fma(pp, wv.x, acc[2 * j2]);
            acc[2 * j2 + 1] = f2fma(pp, wv.y, acc[2 * j2 + 1]);
        }
    }
    float* op = g_q + (size_t)bi * BB * 64 * HW + (size_t)b * 64 * HW + m;
#pragma unroll
    for (int j = 0; j < 32; j++) {
        float2 v = funpack(acc[j]);
        op[(size_t)(2 * j) * HW] = v.x;
        op[(size_t)(2 * j + 1) * HW] = v.y;
    }
}

// ---------------- K2: offset head + kv sample/project (fused, batched) ------
__global__ void k_offkv(const float* __restrict__ x0, const float* __restrict__ x1,
                        const float* __restrict__ dw_w, const float* __restrict__ dw_b,
                        const float* __restrict__ ln_g, const float* __restrict__ ln_b,
                        const float* __restrict__ pw_w,
                        const float* __restrict__ pk_w, const float* __restrict__ pk_b,
                        const float* __restrict__ pv_w, const float* __restrict__ pv_b) {
    __shared__ float off_s[1024];
    __shared__ float stats[32];
    __shared__ float pos_s[16][2];
    __shared__ float wk_s[4096];
    __shared__ float wv_s[4096];
    __shared__ float xs_s[16][64];
    int blk = blockIdx.x, bi = blk >> 7, ib = blk & 127;
    int b = ib >> 4, hk = ib & 15;
    int t = threadIdx.x, wk = t & 15, cq = t >> 4;
    const float* pkw = pk_w + bi * 4096;
    const float* pvw = pv_w + bi * 4096;
    for (int i = t; i < 4096; i += 256) {
        int o = i >> 6, c = i & 63;
        wk_s[c * 64 + o] = pkw[i];
        wv_s[c * 64 + o] = pvw[i];
    }
    const float* dww = dw_w + bi * 1024;
    const float* dwb = dw_b + bi * 64;
    const float* lng = ln_g + bi * 64;
    const float* lnb = ln_b + bi * 64;
    const float* pww = pw_w + bi * 128;
    const float* gq = g_q + (size_t)bi * BB * 64 * HW;
#pragma unroll
    for (int j = 0; j < 4; j++) {
        int c = cq * 4 + j;
        const float* qp = gq + ((size_t)b * 64 + c) * HW + hk * 4 * 64 + wk * 4;
        const float* wp = dww + c * 16;
        float s = dwb[c];
#pragma unroll
        for (int ky = 0; ky < 4; ky++)
#pragma unroll
            for (int kx = 0; kx < 4; kx++)
                s += qp[ky * 64 + kx] * wp[ky * 4 + kx];
        off_s[c * 16 + wk] = s;
    }
    __syncthreads();
    if (t < 16) {
        float s = 0.f, s2 = 0.f;
        for (int c = 0; c < 64; c++) { float v = off_s[c * 16 + t]; s += v; s2 += v * v; }
        float mu = s * (1.f / 64.f);
        float var = s2 * (1.f / 64.f) - mu * mu;
        stats[t * 2] = mu;
        stats[t * 2 + 1] = rsqrtf(var + 1e-5f);
    }
    __syncthreads();
    {
        float mu = stats[wk * 2], inv = stats[wk * 2 + 1];
#pragma unroll
        for (int j = 0; j < 4; j++) {
            int c = cq * 4 + j;
            float v = (off_s[c * 16 + wk] - mu) * inv * lng[c] + lnb[c];
            v = 0.5f * v * (1.f + erff(v * 0.70710678118654752f));
            off_s[c * 16 + wk] = v;
        }
    }
    __syncthreads();
    if (t < 32) {
        int wk2 = t & 15, o = t >> 4;
        const float* pw = pww + o * 64;
        float s = 0.f;
        for (int c = 0; c < 64; c++) s += pw[c] * off_s[c * 16 + wk2];
        float refc = (o == 0) ? ((hk + 0.5f) * (1.f / 15.f) * 2.f - 1.f)
                              : ((wk2 + 0.5f) * (1.f / 15.f) * 2.f - 1.f);
        float p = fminf(fmaxf(s + refc, -1.f), 1.f);
        pos_s[wk2][o] = p;
        g_pos[(size_t)bi * BB * NS * 2 + ((size_t)b * NS + hk * 16 + wk2) * 2 + o] = p;
    }
    __syncthreads();
    const float* xkv = (bi < 2) ? x0 : x1;   // KVJ = {0,0,1}
    const float* pkb = pk_b + bi * 64;
    const float* pvb = pv_b + bi * 64;
    int wi = t >> 5, lane = t & 31;
#pragma unroll
    for (int kk = 0; kk < 2; kk++) {
        int nl = wi * 2 + kk;
        float py = pos_s[nl][0], px = pos_s[nl][1];
        float xi = (px + 1.f) * 31.5f;
        float yi = (py + 1.f) * 31.5f;
        float xf = floorf(xi), yf = floorf(yi);
        float wx = xi - xf, wy = yi - yf;
        int x0i = (int)xf, y0i = (int)yf;
        int x1i = min(x0i + 1, 63), y1i = min(y0i + 1, 63);
        float w00 = (1.f - wy) * (1.f - wx), w01 = (1.f - wy) * wx;
        float w10 = wy * (1.f - wx),         w11 = wy * wx;
#pragma unroll
        for (int ci = 0; ci < 2; ci++) {
            int c = lane + ci * 32;
            const float* p = xkv + ((size_t)b * 128 + c) * HW;
            float s = p[y0i * 64 + x0i] * w00 + p[y0i * 64 + x1i] * w01
                    + p[y1i * 64 + x0i] * w10 + p[y1i * 64 + x1i] * w11;
            xs_s[nl][c] = s;
        }
    }
    __syncwarp();
#pragma unroll
    for (int kk = 0; kk < 2; kk++) {
        int nl = wi * 2 + kk;
        int n = hk * 16 + nl;
        float ak0 = pkb[lane], ak1 = pkb[lane + 32];
        float av0 = pvb[lane], av1 = pvb[lane + 32];
        for (int c = 0; c < 64; c++) {
            float xv = xs_s[nl][c];
            ak0 += wk_s[c * 64 + lane]      * xv;
            ak1 += wk_s[c * 64 + lane + 32] * xv;
            av0 += wv_s[c * 64 + lane]      * xv;
            av1 += wv_s[c * 64 + lane + 32] * xv;
        }
        size_t base = (size_t)bi * BB * 64 * NS;
        g_k[base + ((size_t)b * 64 + lane)      * NS + n] = ak0;
        g_k[base + ((size_t)b * 64 + lane + 32) * NS + n] = ak1;
        g_v[base + ((size_t)b * 64 + lane)      * NS + n] = av0;
        g_v[base + ((size_t)b * 64 + lane + 32) * NS + n] = av1;
    }
}

// ---------------- K3: fused attention, 4 queries/thread (R10 proven form) ---
// block = (bi, b, tile of 512 queries (8 rows), head); 128 threads, 2 blk/SM.
// Double-buffered rpe prefetch (one 2-key group lookahead). exp folded to ex2:
// q scaled by 0.25*log2e, bilinear weights by log2e -> p = exp2f(s).
__global__ void __launch_bounds__(128, 2) k_attn() {
    __shared__ float ks[NS * 16];
    __shared__ float vs[NS * 16];
    __shared__ int boff[NS];
    __shared__ ulonglong2 bwp[NS];
    int blk = blockIdx.x;
    int bi = blk >> 8, inner = blk & 255;
    int h = inner & 3, tile = (inner >> 2) & 7, b = inner >> 5;
    int t = threadIdx.x;
    const float* gk = g_k + (size_t)bi * BB * 64 * NS;
    const float* gv = g_v + (size_t)bi * BB * 64 * NS;
    const float* gp = g_pos + (size_t)bi * BB * NS * 2;
    for (int i = t; i < 4096; i += 128) {
        int c = i >> 8, n = i & 255;
        ks[n * 16 + c] = gk[((size_t)b * 64 + h * 16 + c) * NS + n];
        vs[n * 16 + c] = gv[((size_t)b * 64 + h * 16 + c) * NS + n];
    }
    for (int n = t; n < NS; n += 128) {   // per-key bias precompute (x log2e)
        float py = gp[((size_t)b * NS + n) * 2];
        float px = gp[((size_t)b * NS + n) * 2 + 1];
        float cx = 31.5f * (1.f - px);
        float cy = 31.5f * (1.f - py);
        int ix = (int)floorf(cx), iy = (int)floorf(cy);
        float wx = cx - (float)ix, wy = cy - (float)iy;
        if (ix >= 63) { ix = 62; wx = 1.f; }
        if (iy >= 63) { iy = 62; wy = 1.f; }
        boff[n] = iy * 127 + ix;
        bwp[n] = make_ulonglong2(
            fpack((1.f - wy) * (1.f - wx) * LOG2E, (1.f - wy) * wx * LOG2E),
            fpack(wy * (1.f - wx) * LOG2E,          wy * wx * LOG2E));
    }
    __syncthreads();
    int c63 = t & 63, rg = t >> 6;
    int my0 = tile * 8 + rg * 4;          // rows my0..my0+3
    int m0 = my0 * 64 + c63;
    const float* gq = g_q + (size_t)bi * BB * 64 * HW + ((size_t)b * 64 + h * 16) * HW + m0;
    const float QS = 0.25f * LOG2E;
    u64 q[4][8];
#pragma unroll
    for (int j = 0; j < 8; j++)
#pragma unroll
        for (int i = 0; i < 4; i++)
            q[i][j] = fpack(gq[(size_t)(2 * j) * HW + i * 64]     * QS,
                            gq[(size_t)(2 * j + 1) * HW + i * 64] * QS);
    const float2* rp2 = g_rpe2 + ((size_t)(bi * 4 + h) * 127 * 127) + my0 * 127 + c63;
    float ss0 = 0.f, ss1 = 0.f, ss2 = 0.f, ss3 = 0.f;
    u64 Z = 0ULL;
    u64 acc[4][8];
#pragma unroll
    for (int i = 0; i < 4; i++)
#pragma unroll
        for (int j = 0; j < 8; j++) acc[i][j] = Z;
    // pipeline: groups of 2 keys, one group lookahead; 5 rpe rows per key
    u64 Rc[2][5], Rn[2][5];
#pragma unroll
    for (int j = 0; j < 2; j++) {
        const u64* ap = (const u64*)(rp2 + boff[j]);
#pragma unroll
        for (int r = 0; r < 5; r++) Rc[j][r] = ap[r * 127];
    }
#pragma unroll 2
    for (int g = 0; g < 128; g++) {
        if (g < 127) {
#pragma unroll
            for (int j = 0; j < 2; j++) {
                const u64* ap = (const u64*)(rp2 + boff[2 * g + 2 + j]);
#pragma unroll
                for (int r = 0; r < 5; r++) Rn[j][r] = ap[r * 127];
            }
        }
#pragma unroll
        for (int j = 0; j < 2; j++) {
            int n = 2 * g + j;
            const ulonglong2* kp = (const ulonglong2*)(ks + n * 16);
            ulonglong2 kA = kp[0], kB = kp[1], kC = kp[2], kD = kp[3];
            ulonglong2 w = bwp[n];
            const ulonglong2* vp = (const ulonglong2*)(vs + n * 16);
            ulonglong2 vA = vp[0], vB = vp[1], vC = vp[2], vD = vp[3];
            float p[4];
#pragma unroll
            for (int i = 0; i < 4; i++) {
                // bias seeded into the QK chain (R10 form)
                u64 u = f2fma(w.x, Rc[j][i], f2fma(w.y, Rc[j][i + 1], Z));
                u = f2fma(q[i][0], kA.x, f2fma(q[i][2], kB.x,
                    f2fma(q[i][4], kC.x, f2fma(q[i][6], kD.x, u))));
                u64 v = f2fma(q[i][1], kA.y, f2fma(q[i][3], kB.y,
                    f2fma(q[i][5], kC.y, f2fma(q[i][7], kD.y, Z))));
                float2 s = funpack(f2add(u, v));
                p[i] = exp2f(s.x + s.y);   // bare MUFU.EX2 (log2e pre-folded)
            }
            ss0 += p[0]; ss1 += p[1]; ss2 += p[2]; ss3 += p[3];
#pragma unroll
            for (int i = 0; i < 4; i++) {
                u64 pp = fpack(p[i], p[i]);
                acc[i][0] = f2fma(pp, vA.x, acc[i][0]);
                acc[i][1] = f2fma(pp, vA.y, acc[i][1]);
                acc[i][2] = f2fma(pp, vB.x, acc[i][2]);
                acc[i][3] = f2fma(pp, vB.y, acc[i][3]);
                acc[i][4] = f2fma(pp, vC.x, acc[i][4]);
                acc[i][5] = f2fma(pp, vC.y, acc[i][5]);
                acc[i][6] = f2fma(pp, vD.x, acc[i][6]);
                acc[i][7] = f2fma(pp, vD.y, acc[i][7]);
            }
        }
        if (g < 127) {
#pragma unroll
            for (int j = 0; j < 2; j++)
#pragma unroll
                for (int r = 0; r < 5; r++) Rc[j][r] = Rn[j][r];
        }
    }
    float inv[4] = { 1.f / ss0, 1.f / ss1, 1.f / ss2, 1.f / ss3 };
    float* oa = g_attn + (size_t)bi * BB * 64 * HW + ((size_t)b * 64 + h * 16) * HW + m0;
#pragma unroll
    for (int i = 0; i < 4; i++)
#pragma unroll
        for (int j = 0; j < 8; j++) {
            float2 v = funpack(acc[i][j]);
            oa[(size_t)(2 * j) * HW + i * 64]     = v.x * inv[i];
            oa[(size_t)(2 * j + 1) * HW + i * 64] = v.y * inv[i];
        }
}

// ---------------- K4: out proj + base copy ----------------------------------
// blocks 0..255: out = x[64:128] + proj(attn); blocks 256..1023: base copy.
__global__ void k_oproj(const float* __restrict__ po_w, const float* __restrict__ po_b,
                        const float4* __restrict__ x0f, const float* __restrict__ x1,
                        const float* __restrict__ x2, float* __restrict__ out) {
    int blk = blockIdx.x;
    int t = threadIdx.x;
    if (blk >= 256) {                     // base copy: lvl0 full, lvl1/2 first-64ch
        const int FULL = 1048576;         // float4 per level
        const int HALF = 524288;
        const float4* x1f = (const float4*)x1;
        const float4* x2f = (const float4*)x2;
        float4* outf = (float4*)out;
        for (int i = (blk - 256) * 256 + t; i < FULL + 2 * HALF; i += 768 * 256) {
            if (i < FULL) { outf[i] = x0f[i]; continue; }
            int j = i - FULL;
            int l = (j < HALF) ? 1 : 2;
            int jj = j - (l - 1) * HALF;
            int b = jj >> 16;
            int rem = jj & 65535;
            const float4* src = (l == 1) ? x1f : x2f;
            outf[(size_t)l * FULL + (size_t)b * 131072 + rem] = src[(size_t)b * 131072 + rem];
        }
        return;
    }
    __shared__ float ws[2][4096];
    int lvl2 = blk >> 7, ib = blk & 127;
    if (!lvl2) {
        for (int i = t; i < 4096; i += 256) ws[0][(i & 63) * 64 + (i >> 6)] = po_w[i];
    } else {
        for (int i = t; i < 4096; i += 256) {
            ws[0][(i & 63) * 64 + (i >> 6)] = po_w[4096 + i];
            ws[1][(i & 63) * 64 + (i >> 6)] = po_w[8192 + i];
        }
    }
    __syncthreads();
    int p = ib * 256 + t, b = p >> 12, m = p & 4095;
    u64 acc[32];
    if (!lvl2) {
#pragma unroll
        for (int j = 0; j < 32; j++) acc[j] = fpack(po_b[2 * j], po_b[2 * j + 1]);
        const float* xp = g_attn + (size_t)b * 64 * HW + m;
        for (int c = 0; c < 64; c++) {
            float xv = xp[(size_t)c * HW];
            u64 pp = fpack(xv, xv);
            const ulonglong2* wr = (const ulonglong2*)(ws[0] + c * 64);
#pragma unroll
            for (int j2 = 0; j2 < 16; j2++) {
                ulonglong2 wv = wr[j2];
                acc[2 * j2]     = f2fma(pp, wv.x, acc[2 * j2]);
                acc[2 * j2 + 1] = f2fma(pp, wv.y, acc[2 * j2 + 1]);
            }
        }
        const float* xs = x1 + ((size_t)b * 128 + 64) * HW + m;
        float* op = out + (size_t)1 * BB * 128 * HW + ((size_t)b * 128 + 64) * HW + m;
#pragma unroll
        for (int j = 0; j < 32; j++) {
            float2 v = funpack(acc[j]);
            op[(size_t)(2 * j) * HW]     = xs[(size_t)(2 * j) * HW] + v.x;
            op[(size_t)(2 * j + 1) * HW] = xs[(size_t)(2 * j + 1) * HW] + v.y;
        }
    } else {
#pragma unroll
        for (int j = 0; j < 32; j++)
            acc[j] = fpack(po_b[64 + 2 * j] + po_b[128 + 2 * j],
                           po_b[64 + 2 * j + 1] + po_b[128 + 2 * j + 1]);
        const float* xp1 = g_attn + (size_t)1 * BB * 64 * HW + (size_t)b * 64 * HW + m;
        const float* xp2 = g_attn + (size_t)2 * BB * 64 * HW + (size_t)b * 64 * HW + m;
        for (int c = 0; c < 64; c++) {
            float x1v = xp1[(size_t)c * HW];
            float x2v = xp2[(size_t)c * HW];
            u64 p1 = fpack(x1v, x1v), p2 = fpack(x2v, x2v);
            const ulonglong2* w1 = (const ulonglong2*)(ws[0] + c * 64);
            const ulonglong2* w2 = (const ulonglong2*)(ws[1] + c * 64);
#pragma unroll
            for (int j2 = 0; j2 < 16; j2++) {
                ulonglong2 wv1 = w1[j2], wv2 = w2[j2];
                acc[2 * j2]     = f2fma(p1, wv1.x, f2fma(p2, wv2.x, acc[2 * j2]));
                acc[2 * j2 + 1] = f2fma(p1, wv1.y, f2fma(p2, wv2.y, acc[2 * j2 + 1]));
            }
        }
        const float* xs = x2 + ((size_t)b * 128 + 64) * HW + m;
        float* op = out + (size_t)2 * BB * 128 * HW + ((size_t)b * 128 + 64) * HW + m;
#pragma unroll
        for (int j = 0; j < 32; j++) {
            float2 v = funpack(acc[j]);
            op[(size_t)(2 * j) * HW]     = xs[(size_t)(2 * j) * HW] + v.x;
            op[(size_t)(2 * j + 1) * HW] = xs[(size_t)(2 * j + 1) * HW] + v.y;
        }
    }
}

// ---------------- host ------------------------------------------------------
extern "C" void kernel_launch(void* const* d_in, const int* in_sizes, int n_in,
                              void* d_out, int out_size) {
    const float* x0   = (const float*)d_in[0];
    const float* x1   = (const float*)d_in[1];
    const float* x2   = (const float*)d_in[2];
    const float* pq_w = (const float*)d_in[3];
    const float* pq_b = (const float*)d_in[4];
    const float* dw_w = (const float*)d_in[5];
    const float* dw_b = (const float*)d_in[6];
    const float* ln_g = (const float*)d_in[7];
    const float* ln_b = (const float*)d_in[8];
    const float* pw_w = (const float*)d_in[9];
    const float* pk_w = (const float*)d_in[10];
    const float* pk_b = (const float*)d_in[11];
    const float* pv_w = (const float*)d_in[12];
    const float* pv_b = (const float*)d_in[13];
    const float* po_w = (const float*)d_in[14];
    const float* po_b = (const float*)d_in[15];
    const float* rpe  = (const float*)d_in[16];
    float* out = (float*)d_out;

    k_qproj<<<1141, 256>>>(x1, x2, pq_w, pq_b, rpe);     // 384 proj + 757 rpe-prep
    k_offkv<<<384, 256>>>(x0, x1, dw_w, dw_b, ln_g, ln_b, pw_w,
                          pk_w, pk_b, pv_w, pv_b);
    k_attn<<<768, 128>>>();
    k_oproj<<<1024, 256>>>(po_w, po_b, (const float4*)x0, x1, x2, out);  // 256 proj + 768 copy
}